// round 3
// baseline (speedup 1.0000x reference)
#include <cuda_runtime.h>

#define B_    4
#define T_    4096
#define D_    1024
#define H_    16
#define DH_   64
#define NS_   4
#define CTX_  516
#define Q0_   3580
#define MTOT_ (B_*CTX_)   // 2064

// Scratch (static device globals; no allocation allowed)
__device__ float g_Q[MTOT_*D_];
__device__ float g_K[MTOT_*D_];
__device__ float g_V[MTOT_*D_];
__device__ float g_AO[MTOT_*D_];

// ---------------------------------------------------------------------------
// Zero-fill the structurally-zero output rows (t < Q0 for each batch)
// ---------------------------------------------------------------------------
__global__ void zero_kernel(float* __restrict__ out) {
    size_t idx = (size_t)blockIdx.x * blockDim.x + threadIdx.x;
    const size_t n4 = (size_t)B_ * Q0_ * D_ / 4;
    if (idx < n4) {
        size_t e = idx * 4;
        const size_t perb = (size_t)Q0_ * D_;
        size_t b = e / perb;
        size_t r = e % perb;
        *(float4*)(out + b * (size_t)T_ * D_ + r) = make_float4(0.f, 0.f, 0.f, 0.f);
    }
}

// ---------------------------------------------------------------------------
// Tiled fp32 GEMM: 64x64 block tile, 256 threads, 4x4 per thread, BK=16
// ---------------------------------------------------------------------------
#define BM 64
#define BN 64
#define BK 16

__global__ __launch_bounds__(256) void qkv_gemm(
    const float* __restrict__ x,
    const float* __restrict__ Wq,
    const float* __restrict__ Wk,
    const float* __restrict__ Wv)
{
    const int z = blockIdx.z;
    const float* __restrict__ W = (z == 0) ? Wq : ((z == 1) ? Wk : Wv);
    float* __restrict__ out = (z == 0) ? g_Q : ((z == 1) ? g_K : g_V);

    __shared__ float As[BK][BM];
    __shared__ float Bs[BK][BN + 4];

    const int tid = threadIdx.x;
    const int ty = tid >> 4, tx = tid & 15;
    const int m0 = blockIdx.y * BM, n0 = blockIdx.x * BN;

    // A-load mapping: each thread loads one float4 of one row per k-tile
    const int lrow = tid >> 2;
    const int lk   = (tid & 3) * 4;
    const int m    = m0 + lrow;
    const float* arow = nullptr;
    if (m < MTOT_) {
        int b = m / CTX_, i = m % CTX_;
        int tok = (z == 0) ? (Q0_ + i) : (i < NS_ ? i : (Q0_ + i));
        arow = x + (size_t)(b * T_ + tok) * D_;
    }

    float acc[4][4] = {};

    for (int kt = 0; kt < D_; kt += BK) {
        float4 av = make_float4(0.f, 0.f, 0.f, 0.f);
        if (arow) av = *(const float4*)(arow + kt + lk);
        As[lk + 0][lrow] = av.x;
        As[lk + 1][lrow] = av.y;
        As[lk + 2][lrow] = av.z;
        As[lk + 3][lrow] = av.w;

        float4 bv = *(const float4*)(W + (size_t)(kt + ty) * D_ + (n0 + tx * 4));
        *(float4*)&Bs[ty][tx * 4] = bv;

        __syncthreads();
        #pragma unroll
        for (int kk = 0; kk < BK; kk++) {
            float4 a = *(const float4*)&As[kk][ty * 4];
            float4 b = *(const float4*)&Bs[kk][tx * 4];
            acc[0][0] += a.x * b.x; acc[0][1] += a.x * b.y; acc[0][2] += a.x * b.z; acc[0][3] += a.x * b.w;
            acc[1][0] += a.y * b.x; acc[1][1] += a.y * b.y; acc[1][2] += a.y * b.z; acc[1][3] += a.y * b.w;
            acc[2][0] += a.z * b.x; acc[2][1] += a.z * b.y; acc[2][2] += a.z * b.z; acc[2][3] += a.z * b.w;
            acc[3][0] += a.w * b.x; acc[3][1] += a.w * b.y; acc[3][2] += a.w * b.z; acc[3][3] += a.w * b.w;
        }
        __syncthreads();
    }

    #pragma unroll
    for (int r = 0; r < 4; r++) {
        int mm = m0 + ty * 4 + r;
        if (mm < MTOT_) {
            float4 v = make_float4(acc[r][0], acc[r][1], acc[r][2], acc[r][3]);
            *(float4*)(out + (size_t)mm * D_ + n0 + tx * 4) = v;
        }
    }
}

__global__ __launch_bounds__(256) void oproj_gemm(
    const float* __restrict__ Wo,
    float* __restrict__ out)
{
    __shared__ float As[BK][BM];
    __shared__ float Bs[BK][BN + 4];

    const int tid = threadIdx.x;
    const int ty = tid >> 4, tx = tid & 15;
    const int m0 = blockIdx.y * BM, n0 = blockIdx.x * BN;

    const int lrow = tid >> 2;
    const int lk   = (tid & 3) * 4;
    const int m    = m0 + lrow;
    const float* arow = (m < MTOT_) ? (g_AO + (size_t)m * D_) : nullptr;

    float acc[4][4] = {};

    for (int kt = 0; kt < D_; kt += BK) {
        float4 av = make_float4(0.f, 0.f, 0.f, 0.f);
        if (arow) av = *(const float4*)(arow + kt + lk);
        As[lk + 0][lrow] = av.x;
        As[lk + 1][lrow] = av.y;
        As[lk + 2][lrow] = av.z;
        As[lk + 3][lrow] = av.w;

        float4 bv = *(const float4*)(Wo + (size_t)(kt + ty) * D_ + (n0 + tx * 4));
        *(float4*)&Bs[ty][tx * 4] = bv;

        __syncthreads();
        #pragma unroll
        for (int kk = 0; kk < BK; kk++) {
            float4 a = *(const float4*)&As[kk][ty * 4];
            float4 b = *(const float4*)&Bs[kk][tx * 4];
            acc[0][0] += a.x * b.x; acc[0][1] += a.x * b.y; acc[0][2] += a.x * b.z; acc[0][3] += a.x * b.w;
            acc[1][0] += a.y * b.x; acc[1][1] += a.y * b.y; acc[1][2] += a.y * b.z; acc[1][3] += a.y * b.w;
            acc[2][0] += a.z * b.x; acc[2][1] += a.z * b.y; acc[2][2] += a.z * b.z; acc[2][3] += a.z * b.w;
            acc[3][0] += a.w * b.x; acc[3][1] += a.w * b.y; acc[3][2] += a.w * b.z; acc[3][3] += a.w * b.w;
        }
        __syncthreads();
    }

    #pragma unroll
    for (int r = 0; r < 4; r++) {
        int mm = m0 + ty * 4 + r;
        if (mm < MTOT_) {
            int b = mm / CTX_, i = mm % CTX_;
            float4 v = make_float4(acc[r][0], acc[r][1], acc[r][2], acc[r][3]);
            *(float4*)(out + (size_t)(b * T_ + Q0_ + i) * D_ + n0 + tx * 4) = v;
        }
    }
}

// ---------------------------------------------------------------------------
// Attention: one thread per query, causal over 516-ctx, online softmax.
// K/V tiles of 64 rows staged in smem.
// ---------------------------------------------------------------------------
#define BQ 128
#define KT 64

__global__ __launch_bounds__(BQ) void attn_kernel() {
    const int b = blockIdx.z, h = blockIdx.y, qt = blockIdx.x;
    const int qi = qt * BQ + threadIdx.x;
    const bool act = qi < CTX_;

    float qreg[DH_];
    #pragma unroll
    for (int d = 0; d < DH_; d++) qreg[d] = 0.f;
    if (act) {
        const float* qp = g_Q + (size_t)(b * CTX_ + qi) * D_ + h * DH_;
        #pragma unroll
        for (int d = 0; d < DH_; d += 4) {
            float4 v = *(const float4*)(qp + d);
            qreg[d] = v.x; qreg[d + 1] = v.y; qreg[d + 2] = v.z; qreg[d + 3] = v.w;
        }
    }

    float acc[DH_];
    #pragma unroll
    for (int d = 0; d < DH_; d++) acc[d] = 0.f;
    float mval = -1e30f, lsum = 0.f;

    __shared__ float Ks[KT][DH_];
    __shared__ float Vs[KT][DH_];

    const int jmax = min(CTX_ - 1, qt * BQ + BQ - 1);
    for (int j0 = 0; j0 <= jmax; j0 += KT) {
        // Stage K/V tile (64 rows x 64 cols), coalesced float4
        for (int it = threadIdx.x; it < KT * DH_ / 4; it += BQ) {
            int jj = it >> 4;
            int dd = (it & 15) * 4;
            int j = j0 + jj;
            float4 kv = make_float4(0.f, 0.f, 0.f, 0.f);
            float4 vv = make_float4(0.f, 0.f, 0.f, 0.f);
            if (j < CTX_) {
                size_t off = (size_t)(b * CTX_ + j) * D_ + h * DH_ + dd;
                kv = *(const float4*)(g_K + off);
                vv = *(const float4*)(g_V + off);
            }
            *(float4*)&Ks[jj][dd] = kv;
            *(float4*)&Vs[jj][dd] = vv;
        }
        __syncthreads();

        int jend = act ? min(KT, qi - j0 + 1) : 0;
        for (int jj = 0; jj < jend; jj++) {
            float s0 = 0.f, s1 = 0.f, s2 = 0.f, s3 = 0.f;
            #pragma unroll
            for (int d = 0; d < DH_; d += 4) {
                s0 += qreg[d + 0] * Ks[jj][d + 0];
                s1 += qreg[d + 1] * Ks[jj][d + 1];
                s2 += qreg[d + 2] * Ks[jj][d + 2];
                s3 += qreg[d + 3] * Ks[jj][d + 3];
            }
            float s = ((s0 + s1) + (s2 + s3)) * 0.125f;
            float mn = fmaxf(mval, s);
            float c = __expf(mval - mn);
            float p = __expf(s - mn);
            lsum = lsum * c + p;
            #pragma unroll
            for (int d = 0; d < DH_; d++)
                acc[d] = acc[d] * c + p * Vs[jj][d];
            mval = mn;
        }
        __syncthreads();
    }

    if (act) {
        float inv = 1.f / lsum;
        float* op = g_AO + (size_t)(b * CTX_ + qi) * D_ + h * DH_;
        #pragma unroll
        for (int d = 0; d < DH_; d += 4) {
            float4 v = make_float4(acc[d] * inv, acc[d + 1] * inv,
                                   acc[d + 2] * inv, acc[d + 3] * inv);
            *(float4*)(op + d) = v;
        }
    }
}

// ---------------------------------------------------------------------------
extern "C" void kernel_launch(void* const* d_in, const int* in_sizes, int n_in,
                              void* d_out, int out_size) {
    const float* x  = (const float*)d_in[0];
    const float* Wq = (const float*)d_in[1];
    const float* Wk = (const float*)d_in[2];
    const float* Wv = (const float*)d_in[3];
    const float* Wo = (const float*)d_in[4];
    float* out = (float*)d_out;

    // 1. Zero the structurally-zero rows (output poisoned to 0xAA)
    {
        size_t n4 = (size_t)B_ * Q0_ * D_ / 4;
        int th = 256;
        int bl = (int)((n4 + th - 1) / th);
        zero_kernel<<<bl, th>>>(out);
    }

    // 2. Q/K/V projections for only the 2064 live rows
    {
        dim3 g(D_ / BN, (MTOT_ + BM - 1) / BM, 3);
        qkv_gemm<<<g, 256>>>(x, Wq, Wk, Wv);
    }

    // 3. Causal attention over the 516-entry context
    {
        dim3 g((CTX_ + BQ - 1) / BQ, H_, B_);
        attn_kernel<<<g, BQ>>>();
    }

    // 4. Output projection, scattered to live rows
    {
        dim3 g(D_ / BN, (MTOT_ + BM - 1) / BM, 1);
        oproj_gemm<<<g, 256>>>(Wo, out);
    }
}